// round 6
// baseline (speedup 1.0000x reference)
#include <cuda_runtime.h>
#include <cuda_bf16.h>
#include <math.h>

#define IN_CH    4
#define OUT_CH   8
#define KW       8
#define N_LAYERS 2
#define N_IN     32
#define N_QUBITS 7
#define QDIM     128
#define BATCH    16
#define LIN      2048
#define LOUT     (LIN - KW + 1)   // 2041
#define NGATES   (N_LAYERS * N_QUBITS)

// Packed-duplicated triangle layout of the quadratic forms:
// for each o, groups g = (i, j4) with j4 in [i>>2, 8), 4 entries each,
// entry = (B,B) as float2 where B = 0 (j<i), A_ii (j==i), 2*A_ij (j>i).
#define GROUPS_PER_O  144
#define ENT_PER_O     (GROUPS_PER_O * 4)      // 576
__device__ float2 g_Bp[OUT_CH * ENT_PER_O];
__constant__ unsigned long long c_Bp[OUT_CH * ENT_PER_O];   // 36,864 B

typedef unsigned long long u64;
#define FMA2(d,a,b,c)  asm("fma.rn.f32x2 %0, %1, %2, %3;" : "=l"(d) : "l"(a), "l"(b), "l"(c))
#define PACK2(d,lo,hi) asm("mov.b64 %0, {%1, %2};" : "=l"(d) : "f"(lo), "f"(hi))
#define UNPACK2(lo,hi,s) asm("mov.b64 {%0, %1}, %2;" : "=f"(lo), "=f"(hi) : "l"(s))

// ---------------------------------------------------------------------------
// build kernel: grid (4 i-groups, 8 out-ch), block 256 (8 warps).
// Simulates the 32 basis columns of out-channel o, stores transposed
// interleaved (re,im) float2 with 33-slot row stride, computes 8 rows of
//   A_ij = sum_m z0(m) * (Re_i Re_j + Im_i Im_j), writes packed-dup triangle.
// ---------------------------------------------------------------------------
__global__ __launch_bounds__(256, 1)
void build_kernel(const float* __restrict__ thetas) {
    __shared__ float sU[NGATES][8];
    __shared__ float2 sT[QDIM * 33];     // [m][j] (re,im)

    const int ig = blockIdx.x;
    const int o  = blockIdx.y;
    const int tid  = threadIdx.x;
    const int warp = tid >> 5;
    const int lane = tid & 31;

    if (tid < NGATES) {
        const float* th = thetas + (o * NGATES + tid) * 3;
        float a = th[0], b = th[1], g = th[2];
        float sb, cb; __sincosf(0.5f * b, &sb, &cb);
        float sp, cp; __sincosf(0.5f * (a + g), &sp, &cp);   // ep
        float sm, cm; __sincosf(0.5f * (a - g), &sm, &cm);   // em
        sU[tid][0] =  cp * cb;  sU[tid][1] = -sp * cb;       // u00 = conj(ep)*cb
        sU[tid][2] = -cm * sb;  sU[tid][3] =  sm * sb;       // u01 = -conj(em)*sb
        sU[tid][4] =  cm * sb;  sU[tid][5] =  sm * sb;       // u10 = em*sb
        sU[tid][6] =  cp * cb;  sU[tid][7] =  sp * cb;       // u11 = ep*cb
    }
    __syncthreads();

    // warp simulates columns j = 4*warp + c; amps m = lane + 32*r.
    float re[4][4], im[4][4];
#pragma unroll
    for (int c = 0; c < 4; c++)
#pragma unroll
        for (int r = 0; r < 4; r++) { re[c][r] = 0.f; im[c][r] = 0.f; }
#pragma unroll
    for (int c = 0; c < 4; c++)
        if (lane == 4 * warp + c) re[c][0] = 1.0f;

    for (int l = 0; l < N_LAYERS; l++) {
#pragma unroll
        for (int q = 0; q < N_QUBITS; q++) {
            const float* U = sU[l * N_QUBITS + q];
            float u00r = U[0], u00i = U[1], u01r = U[2], u01i = U[3];
            float u10r = U[4], u10i = U[5], u11r = U[6], u11i = U[7];
            int p = 6 - q;
            if (p >= 5) {
                int d = 1 << (p - 5);
#pragma unroll
                for (int c = 0; c < 4; c++)
#pragma unroll
                    for (int r0 = 0; r0 < 4; r0++) {
                        if (r0 & d) continue;
                        int r1 = r0 | d;
                        float a0r = re[c][r0], a0i = im[c][r0];
                        float a1r = re[c][r1], a1i = im[c][r1];
                        re[c][r0] = u00r*a0r - u00i*a0i + u01r*a1r - u01i*a1i;
                        im[c][r0] = u00r*a0i + u00i*a0r + u01r*a1i + u01i*a1r;
                        re[c][r1] = u10r*a0r - u10i*a0i + u11r*a1r - u11i*a1i;
                        im[c][r1] = u10r*a0i + u10i*a0r + u11r*a1i + u11i*a1r;
                    }
            } else {
                int mask = 1 << p;
                int bit = (lane >> p) & 1;
#pragma unroll
                for (int c = 0; c < 4; c++)
#pragma unroll
                    for (int r = 0; r < 4; r++) {
                        float otr = __shfl_xor_sync(0xffffffffu, re[c][r], mask);
                        float oti = __shfl_xor_sync(0xffffffffu, im[c][r], mask);
                        float sr = re[c][r], si = im[c][r];
                        if (bit == 0) {
                            re[c][r] = u00r*sr - u00i*si + u01r*otr - u01i*oti;
                            im[c][r] = u00r*si + u00i*sr + u01r*oti + u01i*otr;
                        } else {
                            re[c][r] = u10r*otr - u10i*oti + u11r*sr - u11i*si;
                            im[c][r] = u10r*oti + u10i*otr + u11r*si + u11i*sr;
                        }
                    }
            }
        }
#pragma unroll
        for (int r = 0; r < 4; r++) {
            int m = lane + 32 * r;
            int k = __popc(m);
            if (((k * (k - 1)) >> 1) & 1) {
#pragma unroll
                for (int c = 0; c < 4; c++) { re[c][r] = -re[c][r]; im[c][r] = -im[c][r]; }
            }
        }
    }

#pragma unroll
    for (int c = 0; c < 4; c++) {
        int j = 4 * warp + c;
#pragma unroll
        for (int r = 0; r < 4; r++) {
            int m = lane + 32 * r;           // lane stride 33*8B: conflict-free
            sT[m * 33 + j] = make_float2(re[c][r], im[c][r]);
        }
    }
    __syncthreads();

    // Phase C: warp w -> row i = ig*8 + w, lane -> column j.
    {
        const int i = ig * 8 + warp;
        const int j = lane;
        float s0 = 0.f, s1 = 0.f, s2 = 0.f, s3 = 0.f;
#pragma unroll
        for (int m = 0; m < 64; m += 2) {
            float2 ci0 = sT[m*33 + i],     cj0 = sT[m*33 + j];
            float2 ci1 = sT[(m+1)*33 + i], cj1 = sT[(m+1)*33 + j];
            s0 += ci0.x * cj0.x + ci0.y * cj0.y;
            s1 += ci1.x * cj1.x + ci1.y * cj1.y;
        }
#pragma unroll
        for (int m = 64; m < QDIM; m += 2) {
            float2 ci0 = sT[m*33 + i],     cj0 = sT[m*33 + j];
            float2 ci1 = sT[(m+1)*33 + i], cj1 = sT[(m+1)*33 + j];
            s2 += ci0.x * cj0.x + ci0.y * cj0.y;
            s3 += ci1.x * cj1.x + ci1.y * cj1.y;
        }
        float s = (s0 + s1) - (s2 + s3);
        float val = (j < i) ? 0.f : (j == i ? s : 2.f * s);

        // packed-duplicated triangle store: only j-blocks >= i-block
        int cblk = i >> 2;
        if ((j >> 2) >= cblk) {
            int Gi = 4 * (cblk * 8 - (cblk * (cblk - 1)) / 2) + (i & 3) * (8 - cblk);
            int entry = (Gi + (j >> 2) - cblk) * 4 + (j & 3);
            g_Bp[o * ENT_PER_O + entry] = make_float2(val, val);
        }
    }
}

// ---------------------------------------------------------------------------
// conv kernel: 128 threads x 4 consecutive t each; one o per block.
// Packed f32x2 arithmetic: dt pairs (0,1) and (2,3) share each B load.
//   PP[c][k] = (xv[c][k], xv[c][k+1]);  w_j(0,1)=PP[cj][kj], w_j(2,3)=PP[cj][kj+2]
// ---------------------------------------------------------------------------
#define NTHR   128
#define TPT    4
#define TILE_T (NTHR * TPT)        // 512
#define XROW   528

__global__ __launch_bounds__(NTHR)
void conv_kernel(const float* __restrict__ x, float* __restrict__ out) {
    __shared__ alignas(16) float xs[IN_CH][XROW];

    const int b  = blockIdx.y;
    const int o  = blockIdx.z;
    const int t0 = blockIdx.x * TILE_T;
    const int tid = threadIdx.x;

    for (int idx = tid; idx < IN_CH * (TILE_T + KW); idx += NTHR) {
        int c = idx / (TILE_T + KW), i = idx % (TILE_T + KW);
        int gi = t0 + i;
        xs[c][i] = (gi < LIN) ? x[(b * IN_CH + c) * LIN + gi] : 0.f;
    }
    __syncthreads();

    float xv[IN_CH][12];
#pragma unroll
    for (int c = 0; c < IN_CH; c++) {
        const float4* xr = reinterpret_cast<const float4*>(&xs[c][4 * tid]);
        float4 v0 = xr[0], v1 = xr[1], v2 = xr[2];
        xv[c][0]=v0.x; xv[c][1]=v0.y; xv[c][2] =v0.z; xv[c][3] =v0.w;
        xv[c][4]=v1.x; xv[c][5]=v1.y; xv[c][6] =v1.z; xv[c][7] =v1.w;
        xv[c][8]=v2.x; xv[c][9]=v2.y; xv[c][10]=v2.z; xv[c][11]=v2.w;
    }

    // window norms (incremental)
    float n2[TPT];
    {
        float s = 0.f;
#pragma unroll
        for (int c = 0; c < IN_CH; c++)
#pragma unroll
            for (int k = 0; k < KW; k++) { float v = xv[c][k]; s += v * v; }
        n2[0] = s;
#pragma unroll
        for (int dt = 1; dt < TPT; dt++) {
            float d = 0.f;
#pragma unroll
            for (int c = 0; c < IN_CH; c++) {
                float vn = xv[c][dt + 7], vo = xv[c][dt - 1];
                d += vn * vn - vo * vo;
            }
            n2[dt] = n2[dt - 1] + d;
        }
    }

    // packed window pairs
    u64 PP[IN_CH][10];
#pragma unroll
    for (int c = 0; c < IN_CH; c++)
#pragma unroll
        for (int k = 0; k < 10; k++)
            PACK2(PP[c][k], xv[c][k], xv[c][k + 1]);

    const int obase = o * ENT_PER_O;
    u64 acc01 = 0ULL, acc23 = 0ULL;
    int g = 0;
#pragma unroll
    for (int i = 0; i < N_IN; i++) {
        u64 s01 = 0ULL, s23 = 0ULL;
#pragma unroll
        for (int j4 = (i >> 2); j4 < N_IN / 4; j4++) {
#pragma unroll
            for (int jj = 0; jj < 4; jj++) {
                u64 bv = c_Bp[obase + g * 4 + jj];       // (B,B) duplicated
                const int j  = 4 * j4 + jj;
                const int cj = j >> 3, kj = j & 7;
                FMA2(s01, bv, PP[cj][kj],     s01);
                FMA2(s23, bv, PP[cj][kj + 2], s23);
            }
            g++;
        }
        const int ci = i >> 3, ki = i & 7;
        FMA2(acc01, s01, PP[ci][ki],     acc01);
        FMA2(acc23, s23, PP[ci][ki + 2], acc23);
    }

    float a0, a1, a2, a3;
    UNPACK2(a0, a1, acc01);
    UNPACK2(a2, a3, acc23);
    float acc[TPT] = {a0, a1, a2, a3};

    float* po = out + (b * OUT_CH + o) * LOUT;
    const int tb = t0 + 4 * tid;
#pragma unroll
    for (int dt = 0; dt < TPT; dt++) {
        int t = tb + dt;
        if (t < LOUT) po[t] = acc[dt] * __fdividef(1.0f, n2[dt]);
    }
}

// ---------------------------------------------------------------------------
extern "C" void kernel_launch(void* const* d_in, const int* in_sizes, int n_in,
                              void* d_out, int out_size) {
    const float* x      = (const float*)d_in[0];   // (16, 4, 2048) f32
    const float* thetas = (const float*)d_in[1];   // (8, 2, 7, 3) f32
    float* out = (float*)d_out;                    // (16, 8, 2041) f32

    dim3 bgrid(4, OUT_CH);
    build_kernel<<<bgrid, 256>>>(thetas);

    // g_Bp -> constant bank (graph-capturable async D2D, no allocation)
    void* pB = nullptr;
    void* pC = nullptr;
    cudaGetSymbolAddress(&pB, g_Bp);
    cudaGetSymbolAddress(&pC, c_Bp);
    cudaMemcpyAsync(pC, pB, OUT_CH * ENT_PER_O * sizeof(float2),
                    cudaMemcpyDeviceToDevice, 0);

    dim3 cgrid((LOUT + TILE_T - 1) / TILE_T, BATCH, OUT_CH);   // 4 x 16 x 8
    conv_kernel<<<cgrid, NTHR>>>(x, out);
}